// round 16
// baseline (speedup 1.0000x reference)
#include <cuda_runtime.h>
#include <cuda_bf16.h>

#define NN 8192
#define DIN 7
#define DH 8
#define DOUTK 23
#define TS 128                     /* square tile size            */
#define NT (NN / TS)               /* 64 tiles                    */
#define NCTA (NT * (NT + 1) / 2)   /* 2080 CTAs                   */
#define KST (TS / 16)              /* 8 K-steps per tile          */
#define NJKS (NN / 16)             /* 512 global K-steps          */

// -------- device scratch (no allocations allowed) --------
__device__ float g_cA[(NN / 2) * 4];         // per j-pair: {-x0a,-x0b,-x1a,-x1b}
__device__ float4 g_cC[NJKS * 4];            // per (jks,q): {-x2 p0 pair, -x2 p1 pair}
__device__ __nv_bfloat16 g_wvbf[8 * NN];     // rows 0-6 = w*vals, row 7 = w
__device__ uint2 g_bfrag[NJKS * 32];         // preassembled B fragments
__device__ float g_part[NT][NN][8];          // slot s, row i partials (16 MB)
__device__ int g_cnt[NT];                    // per-tile counters (0-init, self-reset)

__device__ __forceinline__ float leaky(float v) {
    return v >= 0.0f ? v : 0.01f * v;
}

// one bf16x2 mask word: lanes of f32x2 = (j even, j odd)
// d = (|ci0-cj0| + |ci1-cj1|) + |ci2-cj2|  -- reference fp32 order, j pre-negated.
// Threshold via FFMA.SAT: m = sat(d*(-2^100) + C'*2^100), C' = nextafter(3.6f).
// Product exact (pow2 scale) => m>0 <=> d <= 3.6f bit-exactly; positives
// saturate to exactly 1.0; bf16 pack = high 16 bits via PRMT.
#define MASKW(out, ci0, ci1, ci2, cj0, cj1, cj2)                          \
    asm("{\n\t"                                                           \
        ".reg .b64 u0,u1,u2;\n\t"                                         \
        ".reg .f32 x0,x1,x2,y0,y1,y2,de,dq,me,mq;\n\t"                    \
        ".reg .b32 ime,imq;\n\t"                                          \
        "add.rn.f32x2 u0, %1, %4;\n\t"                                    \
        "add.rn.f32x2 u1, %2, %5;\n\t"                                    \
        "add.rn.f32x2 u2, %3, %6;\n\t"                                    \
        "mov.b64 {x0,y0}, u0;\n\t"                                        \
        "mov.b64 {x1,y1}, u1;\n\t"                                        \
        "mov.b64 {x2,y2}, u2;\n\t"                                        \
        "abs.f32 x0, x0;\n\t"                                             \
        "abs.f32 x1, x1;\n\t"                                             \
        "abs.f32 x2, x2;\n\t"                                             \
        "abs.f32 y0, y0;\n\t"                                             \
        "abs.f32 y1, y1;\n\t"                                             \
        "abs.f32 y2, y2;\n\t"                                             \
        "add.rn.f32 de, x0, x1;\n\t"                                      \
        "add.rn.f32 de, de, x2;\n\t"                                      \
        "add.rn.f32 dq, y0, y1;\n\t"                                      \
        "add.rn.f32 dq, dq, y2;\n\t"                                      \
        "fma.rn.sat.f32 me, de, 0fF1800000, 0f72666667;\n\t"              \
        "fma.rn.sat.f32 mq, dq, 0fF1800000, 0f72666667;\n\t"              \
        "mov.b32 ime, me;\n\t"                                            \
        "mov.b32 imq, mq;\n\t"                                            \
        "prmt.b32 %0, ime, imq, 0x7632;\n\t"                              \
        "}"                                                               \
        : "=r"(out)                                                       \
        : "l"(ci0), "l"(ci1), "l"(ci2), "l"(cj0), "l"(cj1), "l"(cj2))

#define MMA_BF16(d0, d1, d2, d3, a0, a1, a2, a3, b0, b1)                  \
    asm("mma.sync.aligned.m16n8k16.row.col.f32.bf16.bf16.f32 "            \
        "{%0,%1,%2,%3}, {%4,%5,%6,%7}, {%8,%9}, {%0,%1,%2,%3};"           \
        : "+f"(d0), "+f"(d1), "+f"(d2), "+f"(d3)                          \
        : "r"(a0), "r"(a1), "r"(a2), "r"(a3), "r"(b0), "r"(b1))

// ------- Kernel A: per-node MLP + exp weights + fused fragment build -------
__global__ void __launch_bounds__(32) prep_kernel(
    const float* __restrict__ x,
    const float* __restrict__ W1, const float* __restrict__ b1,
    const float* __restrict__ W2, const float* __restrict__ b2,
    const float* __restrict__ W3, const float* __restrict__ b3)
{
    __shared__ float sW1[DH * DIN], sb1[DH], sW2[DH * DH], sb2[DH],
                     sW3[DOUTK * DH], sb3[DOUTK];
    __shared__ float sx[32 * DIN];
    __shared__ unsigned short s_wvh[8][32];   // bf16 bits, [channel][j-local]
    __shared__ float s_x2[32];                // -x2 per local j
    const int t = threadIdx.x;
    {
        const float* xb = x + blockIdx.x * 32 * DIN;
        for (int k = t; k < 32 * DIN; k += 32) sx[k] = xb[k];
        for (int k = t; k < DH * DIN; k += 32) sW1[k] = W1[k];
        for (int k = t; k < DH * DH; k += 32) sW2[k] = W2[k];
        for (int k = t; k < DOUTK * DH; k += 32) sW3[k] = W3[k];
        if (t < DH) { sb1[t] = b1[t]; sb2[t] = b2[t]; }
        if (t < DOUTK) sb3[t] = b3[t];
    }
    __syncthreads();

    const int j = blockIdx.x * 32 + t;

    float xv[DIN];
#pragma unroll
    for (int k = 0; k < DIN; k++) xv[k] = sx[t * DIN + k];

    float h1[DH];
#pragma unroll
    for (int c = 0; c < DH; c++) {
        float z = sb1[c];
#pragma unroll
        for (int k = 0; k < DIN; k++) z += sW1[c * DIN + k] * xv[k];
        h1[c] = leaky(z);
    }
    float h2[DH];
#pragma unroll
    for (int c = 0; c < DH; c++) {
        float z = sb2[c];
#pragma unroll
        for (int k = 0; k < DH; k++) z += sW2[c * DH + k] * h1[k];
        h2[c] = leaky(z);
    }
    float h3[DOUTK];
#pragma unroll
    for (int c = 0; c < DOUTK; c++) {
        float z = sb3[c];
#pragma unroll
        for (int k = 0; k < DH; k++) z += sW3[c * DH + k] * h2[k];
        h3[c] = z;   // layer 3 is linear
    }

    float s = 0.0f;
#pragma unroll
    for (int k = 0; k < 8; k++) s += h3[DIN + k] * h3[DIN + 8 + k];
    const float w = expf(s);

    // bf16 aggregation channels (w*vals0..6, w)
#pragma unroll
    for (int c = 0; c < 8; c++) {
        const float v = (c < 7) ? w * h3[c] : w;
        const __nv_bfloat16 bf = __float2bfloat16(v);
        g_wvbf[c * NN + j] = bf;                       // for self-subtraction
        s_wvh[c][t] = __bfloat16_as_ushort(bf);
    }

    const int jp = j >> 1, hh = j & 1;
    g_cA[jp * 4 + 0 + hh] = -xv[0];
    g_cA[jp * 4 + 2 + hh] = -xv[1];
    s_x2[t] = -xv[2];

    __syncthreads();

    // ---- fused fragment assembly: this CTA covers 2 global K-steps ----
    const int j0 = blockIdx.x * 32;
    const int jks0 = j0 >> 4;

    // B fragments: m16n8k16 col B, lane (n0=lane/4, q=lane%4):
    //   v.x = {B[k0,n0],B[k0+1,n0]}, v.y = {B[k0+8,n0],B[k0+9,n0]}, k0=2q
#pragma unroll
    for (int e = t; e < 64; e += 32) {
        const int lks = e >> 5, lane = e & 31;
        const int n0 = lane >> 2, q = lane & 3;
        const int bj = lks * 16 + 2 * q;
        uint2 v;
        v.x = (unsigned int)s_wvh[n0][bj] |
              ((unsigned int)s_wvh[n0][bj + 1] << 16);
        v.y = (unsigned int)s_wvh[n0][bj + 8] |
              ((unsigned int)s_wvh[n0][bj + 9] << 16);
        g_bfrag[(jks0 + lks) * 32 + lane] = v;
    }

    // packed x2 table: entry (jks, q) = {-x2 pair p0, -x2 pair p1}
    if (t < 8) {
        const int lks = t >> 2, q = t & 3;
        const int lp0 = lks * 8 + q, lp1 = lp0 + 4;
        g_cC[(jks0 + lks) * 4 + q] =
            make_float4(s_x2[2 * lp0], s_x2[2 * lp0 + 1],
                        s_x2[2 * lp1], s_x2[2 * lp1 + 1]);
    }
}

// ------- Kernel B: symmetric tile-pair masked GEMM + last-CTA epilogue -------
// CTA = upper-triangle tile pair (ta <= tb), 256 threads / 8 warps.
// Phase 1: masks M(ta rows, tb cols) in registers -> GEMM1 + SMEM mask tile.
// Phase 2 (ta != tb): ldmatrix.trans on mask tile -> M^T fragments -> GEMM2.
__global__ void __launch_bounds__(256, 4) pairmma_kernel(
    const float* __restrict__ x,
    const float* __restrict__ We, const float* __restrict__ be,
    const float* __restrict__ Wd, const float* __restrict__ bd,
    float* __restrict__ out)
{
    __shared__ unsigned int s_mask[TS * 64];         // 32 KB swizzled mask tile
    __shared__ uint2 s_bfA[KST * 32];                //  2 KB wv frags, tile ta
    __shared__ uint2 s_bfB[KST * 32];                //  2 KB wv frags, tile tb
    __shared__ float4 s_cA[TS / 2];                  //  1 KB j-pair x0/x1 (tb)
    __shared__ float4 s_cC[KST * 4];                 //  0.5 KB packed x2 (tb)
    __shared__ unsigned long long s_ci[TS * 3];      //  3 KB dup i-coords (ta)
    __shared__ float sWe[DH * 2 * DIN], sbe[DH], sWd[DIN * DH], sbd[DIN];
    __shared__ int s_lastA, s_lastB;

    const int tid = threadIdx.x, wid = tid >> 5, lane = tid & 31;
    const int g = lane >> 2, q = lane & 3;

    // decode upper-triangle pair (ta <= tb)
    int rem = blockIdx.x, ta = 0;
    while (rem >= NT - ta) { rem -= NT - ta; ta++; }
    const int tb = ta + rem;

    {
        const uint4* gba = reinterpret_cast<const uint4*>(g_bfrag + ta * (KST * 32));
        const uint4* gbb = reinterpret_cast<const uint4*>(g_bfrag + tb * (KST * 32));
        uint4* sa4 = reinterpret_cast<uint4*>(s_bfA);
        uint4* sb4 = reinterpret_cast<uint4*>(s_bfB);
        if (tid < KST * 16) { sa4[tid] = gba[tid]; sb4[tid] = gbb[tid]; }
        if (tid < TS / 2)
            s_cA[tid] = reinterpret_cast<const float4*>(g_cA)[tb * (TS / 2) + tid];
        if (tid < KST * 4) s_cC[tid] = g_cC[tb * (KST * 4) + tid];
        if (tid < TS) {
            const int i = ta * TS + tid;
            const float c0 = x[i * DIN + 0];
            const float c1 = x[i * DIN + 1];
            const float c2 = x[i * DIN + 2];
            unsigned long long d0, d1, d2;
            asm("mov.b64 %0, {%1, %1};" : "=l"(d0) : "f"(c0));
            asm("mov.b64 %0, {%1, %1};" : "=l"(d1) : "f"(c1));
            asm("mov.b64 %0, {%1, %1};" : "=l"(d2) : "f"(c2));
            s_ci[tid * 3 + 0] = d0;
            s_ci[tid * 3 + 1] = d1;
            s_ci[tid * 3 + 2] = d2;
        }
    }
    __syncthreads();

    // ---------------- Phase 1: mask-gen + GEMM1 + mask store ----------------
    const int rA = wid * 16 + g;               // mask row (tile ta local)
    const int rB = rA + 8;
    const int r7 = rA & 7;                     // == rB & 7
    {
        const unsigned long long ciA0 = s_ci[rA * 3 + 0];
        const unsigned long long ciA1 = s_ci[rA * 3 + 1];
        const unsigned long long ciA2 = s_ci[rA * 3 + 2];
        const unsigned long long ciB0 = s_ci[rB * 3 + 0];
        const unsigned long long ciB1 = s_ci[rB * 3 + 1];
        const unsigned long long ciB2 = s_ci[rB * 3 + 2];

        float e0 = 0.f, e1 = 0.f, e2 = 0.f, e3 = 0.f;
        float o0 = 0.f, o1 = 0.f, o2 = 0.f, o3 = 0.f;

        const ulonglong2* cap = reinterpret_cast<const ulonglong2*>(s_cA);
        const ulonglong2* ccp = reinterpret_cast<const ulonglong2*>(s_cC);
        unsigned int* mA = s_mask + rA * 64 + q;   // + chunk*4 added per step
        unsigned int* mB = s_mask + rB * 64 + q;

#pragma unroll
        for (int ks = 0; ks < KST; ks++) {
            const int p0 = ks * 8 + q;
            const int p1 = p0 + 4;
            const ulonglong2 ca0 = cap[p0];
            const ulonglong2 ca1 = cap[p1];
            const ulonglong2 cc = ccp[ks * 4 + q];

            unsigned int a0, a1, a2, a3;
            MASKW(a0, ciA0, ciA1, ciA2, ca0.x, ca0.y, cc.x);
            MASKW(a1, ciB0, ciB1, ciB2, ca0.x, ca0.y, cc.x);
            MASKW(a2, ciA0, ciA1, ciA2, ca1.x, ca1.y, cc.y);
            MASKW(a3, ciB0, ciB1, ciB2, ca1.x, ca1.y, cc.y);

            // swizzled mask-tile stores: chunk = colchunk ^ (row & 7)
            const int c0 = ((2 * ks) ^ r7) * 4;
            const int c1 = ((2 * ks + 1) ^ r7) * 4;
            mA[c0] = a0;
            mB[c0] = a1;
            mA[c1] = a2;
            mB[c1] = a3;

            const uint2 bf = s_bfB[ks * 32 + lane];
            if (ks & 1) {
                MMA_BF16(o0, o1, o2, o3, a0, a1, a2, a3, bf.x, bf.y);
            } else {
                MMA_BF16(e0, e1, e2, e3, a0, a1, a2, a3, bf.x, bf.y);
            }
        }

        const int i0 = ta * TS + rA;
        *reinterpret_cast<float2*>(&g_part[tb][i0][2 * q]) =
            make_float2(e0 + o0, e1 + o1);
        *reinterpret_cast<float2*>(&g_part[tb][i0 + 8][2 * q]) =
            make_float2(e2 + o2, e3 + o3);
    }

    // ---------------- Phase 2: transpose GEMM via ldmatrix.trans ----------------
    if (ta != tb) {
        __syncthreads();   // mask tile complete

        const int R0 = wid * 16;   // M^T row block = M col block
        float e0 = 0.f, e1 = 0.f, e2 = 0.f, e3 = 0.f;
        float o0 = 0.f, o1 = 0.f, o2 = 0.f, o3 = 0.f;

        const int lrow7 = (lane & 7) + ((lane >> 4) << 3);   // 0..15
        const int cbase = (R0 >> 3) + ((lane >> 3) & 1);

#pragma unroll
        for (int ks = 0; ks < KST; ks++) {
            const int row = ks * 16 + lrow7;
            const unsigned int widx = row * 64 + ((cbase ^ (row & 7)) << 2);
            const unsigned int saddr = static_cast<unsigned int>(
                __cvta_generic_to_shared(&s_mask[widx]));
            unsigned int a0, a1, a2, a3;
            asm volatile(
                "ldmatrix.sync.aligned.m8n8.x4.trans.shared.b16 "
                "{%0,%1,%2,%3}, [%4];"
                : "=r"(a0), "=r"(a1), "=r"(a2), "=r"(a3)
                : "r"(saddr));

            const uint2 bf = s_bfA[ks * 32 + lane];
            if (ks & 1) {
                MMA_BF16(o0, o1, o2, o3, a0, a1, a2, a3, bf.x, bf.y);
            } else {
                MMA_BF16(e0, e1, e2, e3, a0, a1, a2, a3, bf.x, bf.y);
            }
        }

        const int i0 = tb * TS + R0 + g;
        *reinterpret_cast<float2*>(&g_part[ta][i0][2 * q]) =
            make_float2(e0 + o0, e1 + o1);
        *reinterpret_cast<float2*>(&g_part[ta][i0 + 8][2 * q]) =
            make_float2(e2 + o2, e3 + o3);
    }

    // ---------------- last-CTA-per-tile epilogue ----------------
    __threadfence();
    __syncthreads();
    if (tid == 0) {
        s_lastA = (atomicAdd(&g_cnt[ta], 1) == NT - 1) ? 1 : 0;
        s_lastB = (ta != tb && atomicAdd(&g_cnt[tb], 1) == NT - 1) ? 1 : 0;
    }
    __syncthreads();
    if (!s_lastA && !s_lastB) return;

    for (int k = tid; k < DH * 2 * DIN; k += 256) sWe[k] = We[k];
    if (tid < DIN * DH) sWd[tid] = Wd[tid];
    if (tid < DH) sbe[tid] = be[tid];
    if (tid < DIN) sbd[tid] = bd[tid];
    __syncthreads();

#pragma unroll 1
    for (int pass = 0; pass < 2; pass++) {
        if (pass == 0 && !s_lastA) continue;
        if (pass == 1 && !s_lastB) continue;
        const int tt = (pass == 0) ? ta : tb;
        if (tid < TS) {
            const int i = tt * TS + tid;

            float a[8];
#pragma unroll
            for (int k = 0; k < 8; k++) a[k] = 0.0f;
#pragma unroll 8
            for (int s = 0; s < NT; s++) {
                const float4* p = reinterpret_cast<const float4*>(&g_part[s][i][0]);
                const float4 pa = p[0], pb = p[1];
                a[0] += pa.x; a[1] += pa.y; a[2] += pa.z; a[3] += pa.w;
                a[4] += pb.x; a[5] += pb.y; a[6] += pb.z; a[7] += pb.w;
            }
            // subtract self contribution exactly as the MMA added it
#pragma unroll
            for (int c = 0; c < 8; c++)
                a[c] -= __bfloat162float(g_wvbf[c * NN + i]);
            const float inv = 1.0f / fmaxf(a[7], 1e-30f);

            float agg[DIN];
#pragma unroll
            for (int k = 0; k < DIN; k++) agg[k] = a[k] * inv;

            float xv[DIN];
#pragma unroll
            for (int k = 0; k < DIN; k++) xv[k] = x[i * DIN + k];

            float codes[DH];
#pragma unroll
            for (int c = 0; c < DH; c++) {
                float z = sbe[c];
#pragma unroll
                for (int k = 0; k < DIN; k++) z += sWe[c * (2 * DIN) + k] * xv[k];
#pragma unroll
                for (int k = 0; k < DIN; k++)
                    z += sWe[c * (2 * DIN) + DIN + k] * agg[k];
                codes[c] = leaky(z);
            }
#pragma unroll
            for (int d = 0; d < DIN; d++) {
                float z = sbd[d];
#pragma unroll
                for (int c = 0; c < DH; c++) z += sWd[d * DH + c] * codes[c];
                out[i * DIN + d] = z;
            }
        }
    }
    if (tid == 0) {
        if (s_lastA) g_cnt[ta] = 0;    // self-reset for next graph replay
        if (s_lastB) g_cnt[tb] = 0;
    }
}

// ---------------- launch ----------------
extern "C" void kernel_launch(void* const* d_in, const int* in_sizes, int n_in,
                              void* d_out, int out_size)
{
    const float* x  = (const float*)d_in[0];
    const float* W1 = (const float*)d_in[1];
    const float* b1 = (const float*)d_in[2];
    const float* W2 = (const float*)d_in[3];
    const float* b2 = (const float*)d_in[4];
    const float* W3 = (const float*)d_in[5];
    const float* b3 = (const float*)d_in[6];
    const float* We = (const float*)d_in[7];
    const float* be = (const float*)d_in[8];
    const float* Wd = (const float*)d_in[9];
    const float* bd = (const float*)d_in[10];
    float* out = (float*)d_out;

    prep_kernel<<<NN / 32, 32>>>(x, W1, b1, W2, b2, W3, b3);
    pairmma_kernel<<<NCTA, 256>>>(x, We, be, Wd, bd, out);
}

// round 17
// speedup vs baseline: 1.0056x; 1.0056x over previous
#include <cuda_runtime.h>
#include <cuda_bf16.h>

#define NN 8192
#define DIN 7
#define DH 8
#define DOUTK 23
#define TS 128                     /* square tile size            */
#define NT (NN / TS)               /* 64 tiles                    */
#define NCTA (NT * (NT + 1) / 2)   /* 2080 CTAs                   */
#define KST (TS / 16)              /* 8 K-steps per tile          */
#define NJKS (NN / 16)             /* 512 global K-steps          */

// -------- device scratch (no allocations allowed) --------
__device__ float g_cA[(NN / 2) * 4];         // per j-pair: {-x0a,-x0b,-x1a,-x1b}
__device__ float4 g_cC[NJKS * 4];            // per (jks,q): {-x2 p0 pair, -x2 p1 pair}
__device__ __nv_bfloat16 g_wvbf[8 * NN];     // rows 0-6 = w*vals, row 7 = w
__device__ uint2 g_bfrag[NJKS * 32];         // preassembled B fragments
__device__ float g_part[NT][NN][8];          // slot s, row i partials (16 MB)
__device__ int g_cnt[NT];                    // per-tile counters (0-init, self-reset)

__device__ __forceinline__ float leaky(float v) {
    return v >= 0.0f ? v : 0.01f * v;
}

// one bf16x2 mask word: lanes of f32x2 = (j even, j odd)
// d = (|ci0-cj0| + |ci1-cj1|) + |ci2-cj2|  -- reference fp32 order, j pre-negated.
// Threshold via FFMA.SAT: m = sat(d*(-2^100) + C'*2^100), C' = nextafter(3.6f).
// Product exact (pow2 scale) => m>0 <=> d <= 3.6f bit-exactly; positives
// saturate to exactly 1.0; bf16 pack = high 16 bits via PRMT.
#define MASKW(out, ci0, ci1, ci2, cj0, cj1, cj2)                          \
    asm("{\n\t"                                                           \
        ".reg .b64 u0,u1,u2;\n\t"                                         \
        ".reg .f32 x0,x1,x2,y0,y1,y2,de,dq,me,mq;\n\t"                    \
        ".reg .b32 ime,imq;\n\t"                                          \
        "add.rn.f32x2 u0, %1, %4;\n\t"                                    \
        "add.rn.f32x2 u1, %2, %5;\n\t"                                    \
        "add.rn.f32x2 u2, %3, %6;\n\t"                                    \
        "mov.b64 {x0,y0}, u0;\n\t"                                        \
        "mov.b64 {x1,y1}, u1;\n\t"                                        \
        "mov.b64 {x2,y2}, u2;\n\t"                                        \
        "abs.f32 x0, x0;\n\t"                                             \
        "abs.f32 x1, x1;\n\t"                                             \
        "abs.f32 x2, x2;\n\t"                                             \
        "abs.f32 y0, y0;\n\t"                                             \
        "abs.f32 y1, y1;\n\t"                                             \
        "abs.f32 y2, y2;\n\t"                                             \
        "add.rn.f32 de, x0, x1;\n\t"                                      \
        "add.rn.f32 de, de, x2;\n\t"                                      \
        "add.rn.f32 dq, y0, y1;\n\t"                                      \
        "add.rn.f32 dq, dq, y2;\n\t"                                      \
        "fma.rn.sat.f32 me, de, 0fF1800000, 0f72666667;\n\t"              \
        "fma.rn.sat.f32 mq, dq, 0fF1800000, 0f72666667;\n\t"              \
        "mov.b32 ime, me;\n\t"                                            \
        "mov.b32 imq, mq;\n\t"                                            \
        "prmt.b32 %0, ime, imq, 0x7632;\n\t"                              \
        "}"                                                               \
        : "=r"(out)                                                       \
        : "l"(ci0), "l"(ci1), "l"(ci2), "l"(cj0), "l"(cj1), "l"(cj2))

#define MMA_BF16(d0, d1, d2, d3, a0, a1, a2, a3, b0, b1)                  \
    asm("mma.sync.aligned.m16n8k16.row.col.f32.bf16.bf16.f32 "            \
        "{%0,%1,%2,%3}, {%4,%5,%6,%7}, {%8,%9}, {%0,%1,%2,%3};"           \
        : "+f"(d0), "+f"(d1), "+f"(d2), "+f"(d3)                          \
        : "r"(a0), "r"(a1), "r"(a2), "r"(a3), "r"(b0), "r"(b1))

// ------- Kernel A: per-node MLP + exp weights + fused fragment build -------
__global__ void __launch_bounds__(32) prep_kernel(
    const float* __restrict__ x,
    const float* __restrict__ W1, const float* __restrict__ b1,
    const float* __restrict__ W2, const float* __restrict__ b2,
    const float* __restrict__ W3, const float* __restrict__ b3)
{
    __shared__ float sW1[DH * DIN], sb1[DH], sW2[DH * DH], sb2[DH],
                     sW3[DOUTK * DH], sb3[DOUTK];
    __shared__ float sx[32 * DIN];
    __shared__ unsigned short s_wvh[8][32];   // bf16 bits, [channel][j-local]
    __shared__ float s_x2[32];                // -x2 per local j
    const int t = threadIdx.x;
    {
        const float* xb = x + blockIdx.x * 32 * DIN;
        for (int k = t; k < 32 * DIN; k += 32) sx[k] = xb[k];
        for (int k = t; k < DH * DIN; k += 32) sW1[k] = W1[k];
        for (int k = t; k < DH * DH; k += 32) sW2[k] = W2[k];
        for (int k = t; k < DOUTK * DH; k += 32) sW3[k] = W3[k];
        if (t < DH) { sb1[t] = b1[t]; sb2[t] = b2[t]; }
        if (t < DOUTK) sb3[t] = b3[t];
    }
    __syncthreads();

    const int j = blockIdx.x * 32 + t;

    float xv[DIN];
#pragma unroll
    for (int k = 0; k < DIN; k++) xv[k] = sx[t * DIN + k];

    float h1[DH];
#pragma unroll
    for (int c = 0; c < DH; c++) {
        float z = sb1[c];
#pragma unroll
        for (int k = 0; k < DIN; k++) z += sW1[c * DIN + k] * xv[k];
        h1[c] = leaky(z);
    }
    float h2[DH];
#pragma unroll
    for (int c = 0; c < DH; c++) {
        float z = sb2[c];
#pragma unroll
        for (int k = 0; k < DH; k++) z += sW2[c * DH + k] * h1[k];
        h2[c] = leaky(z);
    }
    float h3[DOUTK];
#pragma unroll
    for (int c = 0; c < DOUTK; c++) {
        float z = sb3[c];
#pragma unroll
        for (int k = 0; k < DH; k++) z += sW3[c * DH + k] * h2[k];
        h3[c] = z;   // layer 3 is linear
    }

    float s = 0.0f;
#pragma unroll
    for (int k = 0; k < 8; k++) s += h3[DIN + k] * h3[DIN + 8 + k];
    const float w = expf(s);

    // bf16 aggregation channels (w*vals0..6, w)
#pragma unroll
    for (int c = 0; c < 8; c++) {
        const float v = (c < 7) ? w * h3[c] : w;
        const __nv_bfloat16 bf = __float2bfloat16(v);
        g_wvbf[c * NN + j] = bf;                       // for self-subtraction
        s_wvh[c][t] = __bfloat16_as_ushort(bf);
    }

    const int jp = j >> 1, hh = j & 1;
    g_cA[jp * 4 + 0 + hh] = -xv[0];
    g_cA[jp * 4 + 2 + hh] = -xv[1];
    s_x2[t] = -xv[2];

    __syncthreads();

    // ---- fused fragment assembly: this CTA covers 2 global K-steps ----
    const int j0 = blockIdx.x * 32;
    const int jks0 = j0 >> 4;

    // B fragments: m16n8k16 col B, lane (n0=lane/4, q=lane%4):
    //   v.x = {B[k0,n0],B[k0+1,n0]}, v.y = {B[k0+8,n0],B[k0+9,n0]}, k0=2q
#pragma unroll
    for (int e = t; e < 64; e += 32) {
        const int lks = e >> 5, lane = e & 31;
        const int n0 = lane >> 2, q = lane & 3;
        const int bj = lks * 16 + 2 * q;
        uint2 v;
        v.x = (unsigned int)s_wvh[n0][bj] |
              ((unsigned int)s_wvh[n0][bj + 1] << 16);
        v.y = (unsigned int)s_wvh[n0][bj + 8] |
              ((unsigned int)s_wvh[n0][bj + 9] << 16);
        g_bfrag[(jks0 + lks) * 32 + lane] = v;
    }

    // packed x2 table: entry (jks, q) = {-x2 pair p0, -x2 pair p1}
    if (t < 8) {
        const int lks = t >> 2, q = t & 3;
        const int lp0 = lks * 8 + q, lp1 = lp0 + 4;
        g_cC[(jks0 + lks) * 4 + q] =
            make_float4(s_x2[2 * lp0], s_x2[2 * lp0 + 1],
                        s_x2[2 * lp1], s_x2[2 * lp1 + 1]);
    }
}

// ------- Kernel B: symmetric tile-pair masked GEMM + last-CTA epilogue -------
// CTA = upper-triangle tile pair (ta <= tb), 256 threads / 8 warps.
// Phase 1: masks M(ta rows, tb cols) in registers -> GEMM1 + SMEM mask tile.
// Phase 2 (ta != tb): ldmatrix.trans on mask tile -> M^T fragments -> GEMM2.
// NOTE: occupancy 3 (not 4): 4 pinned regs at exactly 64 and spilled the hot
// loop (R16: 26.6M issued instrs vs ~12M expected). 3 allows ~85 regs, no spill.
__global__ void __launch_bounds__(256, 3) pairmma_kernel(
    const float* __restrict__ x,
    const float* __restrict__ We, const float* __restrict__ be,
    const float* __restrict__ Wd, const float* __restrict__ bd,
    float* __restrict__ out)
{
    __shared__ unsigned int s_mask[TS * 64];         // 32 KB swizzled mask tile
    __shared__ uint2 s_bfA[KST * 32];                //  2 KB wv frags, tile ta
    __shared__ uint2 s_bfB[KST * 32];                //  2 KB wv frags, tile tb
    __shared__ float4 s_cA[TS / 2];                  //  1 KB j-pair x0/x1 (tb)
    __shared__ float4 s_cC[KST * 4];                 //  0.5 KB packed x2 (tb)
    __shared__ unsigned long long s_ci[TS * 3];      //  3 KB dup i-coords (ta)
    __shared__ float sWe[DH * 2 * DIN], sbe[DH], sWd[DIN * DH], sbd[DIN];
    __shared__ int s_lastA, s_lastB;

    const int tid = threadIdx.x, wid = tid >> 5, lane = tid & 31;
    const int g = lane >> 2, q = lane & 3;

    // decode upper-triangle pair (ta <= tb)
    int rem = blockIdx.x, ta = 0;
    while (rem >= NT - ta) { rem -= NT - ta; ta++; }
    const int tb = ta + rem;

    {
        const uint4* gba = reinterpret_cast<const uint4*>(g_bfrag + ta * (KST * 32));
        const uint4* gbb = reinterpret_cast<const uint4*>(g_bfrag + tb * (KST * 32));
        uint4* sa4 = reinterpret_cast<uint4*>(s_bfA);
        uint4* sb4 = reinterpret_cast<uint4*>(s_bfB);
        if (tid < KST * 16) { sa4[tid] = gba[tid]; sb4[tid] = gbb[tid]; }
        if (tid < TS / 2)
            s_cA[tid] = reinterpret_cast<const float4*>(g_cA)[tb * (TS / 2) + tid];
        if (tid < KST * 4) s_cC[tid] = g_cC[tb * (KST * 4) + tid];
        if (tid < TS) {
            const int i = ta * TS + tid;
            const float c0 = x[i * DIN + 0];
            const float c1 = x[i * DIN + 1];
            const float c2 = x[i * DIN + 2];
            unsigned long long d0, d1, d2;
            asm("mov.b64 %0, {%1, %1};" : "=l"(d0) : "f"(c0));
            asm("mov.b64 %0, {%1, %1};" : "=l"(d1) : "f"(c1));
            asm("mov.b64 %0, {%1, %1};" : "=l"(d2) : "f"(c2));
            s_ci[tid * 3 + 0] = d0;
            s_ci[tid * 3 + 1] = d1;
            s_ci[tid * 3 + 2] = d2;
        }
    }
    __syncthreads();

    // ---------------- Phase 1: mask-gen + GEMM1 + mask store ----------------
    const int rA = wid * 16 + g;               // mask row (tile ta local)
    const int rB = rA + 8;
    const int r7 = rA & 7;                     // == rB & 7
    {
        const unsigned long long ciA0 = s_ci[rA * 3 + 0];
        const unsigned long long ciA1 = s_ci[rA * 3 + 1];
        const unsigned long long ciA2 = s_ci[rA * 3 + 2];
        const unsigned long long ciB0 = s_ci[rB * 3 + 0];
        const unsigned long long ciB1 = s_ci[rB * 3 + 1];
        const unsigned long long ciB2 = s_ci[rB * 3 + 2];

        float e0 = 0.f, e1 = 0.f, e2 = 0.f, e3 = 0.f;
        float o0 = 0.f, o1 = 0.f, o2 = 0.f, o3 = 0.f;

        const ulonglong2* cap = reinterpret_cast<const ulonglong2*>(s_cA);
        const ulonglong2* ccp = reinterpret_cast<const ulonglong2*>(s_cC);
        unsigned int* mA = s_mask + rA * 64 + q;   // + chunk*4 added per step
        unsigned int* mB = s_mask + rB * 64 + q;

#pragma unroll
        for (int ks = 0; ks < KST; ks++) {
            const int p0 = ks * 8 + q;
            const int p1 = p0 + 4;
            const ulonglong2 ca0 = cap[p0];
            const ulonglong2 ca1 = cap[p1];
            const ulonglong2 cc = ccp[ks * 4 + q];

            unsigned int a0, a1, a2, a3;
            MASKW(a0, ciA0, ciA1, ciA2, ca0.x, ca0.y, cc.x);
            MASKW(a1, ciB0, ciB1, ciB2, ca0.x, ca0.y, cc.x);
            MASKW(a2, ciA0, ciA1, ciA2, ca1.x, ca1.y, cc.y);
            MASKW(a3, ciB0, ciB1, ciB2, ca1.x, ca1.y, cc.y);

            // swizzled mask-tile stores: chunk = colchunk ^ (row & 7)
            const int c0 = ((2 * ks) ^ r7) * 4;
            const int c1 = ((2 * ks + 1) ^ r7) * 4;
            mA[c0] = a0;
            mB[c0] = a1;
            mA[c1] = a2;
            mB[c1] = a3;

            const uint2 bf = s_bfB[ks * 32 + lane];
            if (ks & 1) {
                MMA_BF16(o0, o1, o2, o3, a0, a1, a2, a3, bf.x, bf.y);
            } else {
                MMA_BF16(e0, e1, e2, e3, a0, a1, a2, a3, bf.x, bf.y);
            }
        }

        const int i0 = ta * TS + rA;
        *reinterpret_cast<float2*>(&g_part[tb][i0][2 * q]) =
            make_float2(e0 + o0, e1 + o1);
        *reinterpret_cast<float2*>(&g_part[tb][i0 + 8][2 * q]) =
            make_float2(e2 + o2, e3 + o3);
    }

    // ---------------- Phase 2: transpose GEMM via ldmatrix.trans ----------------
    if (ta != tb) {
        __syncthreads();   // mask tile complete

        const int R0 = wid * 16;   // M^T row block = M col block
        float e0 = 0.f, e1 = 0.f, e2 = 0.f, e3 = 0.f;
        float o0 = 0.f, o1 = 0.f, o2 = 0.f, o3 = 0.f;

        const int lrow7 = (lane & 7) + ((lane >> 4) << 3);   // 0..15
        const int cbase = (R0 >> 3) + ((lane >> 3) & 1);

#pragma unroll
        for (int ks = 0; ks < KST; ks++) {
            const int row = ks * 16 + lrow7;
            const unsigned int widx = row * 64 + ((cbase ^ (row & 7)) << 2);
            const unsigned int saddr = static_cast<unsigned int>(
                __cvta_generic_to_shared(&s_mask[widx]));
            unsigned int a0, a1, a2, a3;
            asm volatile(
                "ldmatrix.sync.aligned.m8n8.x4.trans.shared.b16 "
                "{%0,%1,%2,%3}, [%4];"
                : "=r"(a0), "=r"(a1), "=r"(a2), "=r"(a3)
                : "r"(saddr));

            const uint2 bf = s_bfA[ks * 32 + lane];
            if (ks & 1) {
                MMA_BF16(o0, o1, o2, o3, a0, a1, a2, a3, bf.x, bf.y);
            } else {
                MMA_BF16(e0, e1, e2, e3, a0, a1, a2, a3, bf.x, bf.y);
            }
        }

        const int i0 = tb * TS + R0 + g;
        *reinterpret_cast<float2*>(&g_part[ta][i0][2 * q]) =
            make_float2(e0 + o0, e1 + o1);
        *reinterpret_cast<float2*>(&g_part[ta][i0 + 8][2 * q]) =
            make_float2(e2 + o2, e3 + o3);
    }

    // ---------------- last-CTA-per-tile epilogue ----------------
    __threadfence();
    __syncthreads();
    if (tid == 0) {
        s_lastA = (atomicAdd(&g_cnt[ta], 1) == NT - 1) ? 1 : 0;
        s_lastB = (ta != tb && atomicAdd(&g_cnt[tb], 1) == NT - 1) ? 1 : 0;
    }
    __syncthreads();
    if (!s_lastA && !s_lastB) return;

    for (int k = tid; k < DH * 2 * DIN; k += 256) sWe[k] = We[k];
    if (tid < DIN * DH) sWd[tid] = Wd[tid];
    if (tid < DH) sbe[tid] = be[tid];
    if (tid < DIN) sbd[tid] = bd[tid];
    __syncthreads();

#pragma unroll 1
    for (int pass = 0; pass < 2; pass++) {
        if (pass == 0 && !s_lastA) continue;
        if (pass == 1 && !s_lastB) continue;
        const int tt = (pass == 0) ? ta : tb;
        if (tid < TS) {
            const int i = tt * TS + tid;

            float a[8];
#pragma unroll
            for (int k = 0; k < 8; k++) a[k] = 0.0f;
#pragma unroll 8
            for (int s = 0; s < NT; s++) {
                const float4* p = reinterpret_cast<const float4*>(&g_part[s][i][0]);
                const float4 pa = p[0], pb = p[1];
                a[0] += pa.x; a[1] += pa.y; a[2] += pa.z; a[3] += pa.w;
                a[4] += pb.x; a[5] += pb.y; a[6] += pb.z; a[7] += pb.w;
            }
            // subtract self contribution exactly as the MMA added it
#pragma unroll
            for (int c = 0; c < 8; c++)
                a[c] -= __bfloat162float(g_wvbf[c * NN + i]);
            const float inv = 1.0f / fmaxf(a[7], 1e-30f);

            float agg[DIN];
#pragma unroll
            for (int k = 0; k < DIN; k++) agg[k] = a[k] * inv;

            float xv[DIN];
#pragma unroll
            for (int k = 0; k < DIN; k++) xv[k] = x[i * DIN + k];

            float codes[DH];
#pragma unroll
            for (int c = 0; c < DH; c++) {
                float z = sbe[c];
#pragma unroll
                for (int k = 0; k < DIN; k++) z += sWe[c * (2 * DIN) + k] * xv[k];
#pragma unroll
                for (int k = 0; k < DIN; k++)
                    z += sWe[c * (2 * DIN) + DIN + k] * agg[k];
                codes[c] = leaky(z);
            }
#pragma unroll
            for (int d = 0; d < DIN; d++) {
                float z = sbd[d];
#pragma unroll
                for (int c = 0; c < DH; c++) z += sWd[d * DH + c] * codes[c];
                out[i * DIN + d] = z;
            }
        }
    }
    if (tid == 0) {
        if (s_lastA) g_cnt[ta] = 0;    // self-reset for next graph replay
        if (s_lastB) g_cnt[tb] = 0;
    }
}

// ---------------- launch ----------------
extern "C" void kernel_launch(void* const* d_in, const int* in_sizes, int n_in,
                              void* d_out, int out_size)
{
    const float* x  = (const float*)d_in[0];
    const float* W1 = (const float*)d_in[1];
    const float* b1 = (const float*)d_in[2];
    const float* W2 = (const float*)d_in[3];
    const float* b2 = (const float*)d_in[4];
    const float* W3 = (const float*)d_in[5];
    const float* b3 = (const float*)d_in[6];
    const float* We = (const float*)d_in[7];
    const float* be = (const float*)d_in[8];
    const float* Wd = (const float*)d_in[9];
    const float* bd = (const float*)d_in[10];
    float* out = (float*)d_out;

    prep_kernel<<<NN / 32, 32>>>(x, W1, b1, W2, b2, W3, b3);
    pairmma_kernel<<<NCTA, 256>>>(x, We, be, Wd, bd, out);
}